// round 2
// baseline (speedup 1.0000x reference)
#include <cuda_runtime.h>
#include <cuda_bf16.h>
#include <math.h>

// ---------------------------------------------------------------------------
// Problem constants (compiled in; out_h/out_w inputs ignored)
// ---------------------------------------------------------------------------
#define M_TOK   11520          // 2 * 5760 tokens
#define DIM     512
#define HID     1960           // 40 * 49
#define BPRIME  16             // 11520 / 720
#define NCH     40             // HID / 49
#define OH      20
#define OW      36
#define LVEC    720            // OH*OW
#define HP      66             // 60 + 2*3
#define WP      114            // 108 + 2*3
#define NPIX    (BPRIME*NCH*HP*WP)   // 4,815,360

// Scratch (allocation-free rule: __device__ globals)
__device__ float g_h  [(size_t)M_TOK * HID];   // GEMM1 output
__device__ float g_pix[(size_t)NPIX];          // folded / normalized / masked
__device__ float g_y  [(size_t)M_TOK * HID];   // unfolded

// ---------------------------------------------------------------------------
// SGEMM: C[m,n] = sum_k f(A[m,k]) * B[n,k] + bias[n]
// A row-major [M,K], B row-major [N,K] (both K-contiguous), C row-major [M,N]
// BM=BN=128, BK=16, 256 threads, 8x8 per-thread microtile.
// ---------------------------------------------------------------------------
#define BM 128
#define BN 128
#define BK 16
#define LDT 132   // padded leading dim for smem tiles (keeps 16B alignment)

__device__ __forceinline__ float gelu_exact(float v) {
    return 0.5f * v * (1.0f + erff(v * 0.70710678118654752f));
}

template<bool GELU_A>
__global__ __launch_bounds__(256)
void sgemm_tn_bias(const float* __restrict__ A, const float* __restrict__ B,
                   const float* __restrict__ bias, float* __restrict__ C,
                   int M, int N, int K)
{
    __shared__ float As[BK][LDT];
    __shared__ float Bs[BK][LDT];

    const int tid = threadIdx.x;
    const int tx  = tid & 15;        // 0..15  -> N direction
    const int ty  = tid >> 4;        // 0..15  -> M direction
    const int m0  = blockIdx.y * BM;
    const int n0  = blockIdx.x * BN;

    float acc[8][8];
#pragma unroll
    for (int i = 0; i < 8; i++)
#pragma unroll
        for (int j = 0; j < 8; j++) acc[i][j] = 0.0f;

    const int nKT = (K + BK - 1) / BK;
    for (int kt = 0; kt < nKT; kt++) {
        const int k0 = kt * BK;

        // ---- load A tile (128 rows x 16 k), transposed into As[k][m] ----
#pragma unroll
        for (int it = 0; it < 2; it++) {
            int f4  = tid + it * 256;          // 0..511
            int row = f4 >> 2;                 // 0..127
            int c4  = f4 & 3;                  // 0..3
            int k   = k0 + c4 * 4;
            int gm  = m0 + row;
            float4 v = make_float4(0.f, 0.f, 0.f, 0.f);
            if (gm < M && k < K) {             // K multiple of 4: full-or-none
                v = *reinterpret_cast<const float4*>(A + (size_t)gm * K + k);
                if (GELU_A) {
                    v.x = gelu_exact(v.x); v.y = gelu_exact(v.y);
                    v.z = gelu_exact(v.z); v.w = gelu_exact(v.w);
                }
            }
            As[c4*4+0][row] = v.x;
            As[c4*4+1][row] = v.y;
            As[c4*4+2][row] = v.z;
            As[c4*4+3][row] = v.w;
        }
        // ---- load B tile (128 n x 16 k), transposed into Bs[k][n] ----
#pragma unroll
        for (int it = 0; it < 2; it++) {
            int f4  = tid + it * 256;
            int row = f4 >> 2;
            int c4  = f4 & 3;
            int k   = k0 + c4 * 4;
            int gn  = n0 + row;
            float4 v = make_float4(0.f, 0.f, 0.f, 0.f);
            if (gn < N && k < K) {
                v = *reinterpret_cast<const float4*>(B + (size_t)gn * K + k);
            }
            Bs[c4*4+0][row] = v.x;
            Bs[c4*4+1][row] = v.y;
            Bs[c4*4+2][row] = v.z;
            Bs[c4*4+3][row] = v.w;
        }
        __syncthreads();

#pragma unroll
        for (int k = 0; k < BK; k++) {
            float4 a0 = *reinterpret_cast<const float4*>(&As[k][ty * 8 + 0]);
            float4 a1 = *reinterpret_cast<const float4*>(&As[k][ty * 8 + 4]);
            float4 b0 = *reinterpret_cast<const float4*>(&Bs[k][tx * 8 + 0]);
            float4 b1 = *reinterpret_cast<const float4*>(&Bs[k][tx * 8 + 4]);
            float ra[8] = {a0.x, a0.y, a0.z, a0.w, a1.x, a1.y, a1.z, a1.w};
            float rb[8] = {b0.x, b0.y, b0.z, b0.w, b1.x, b1.y, b1.z, b1.w};
#pragma unroll
            for (int i = 0; i < 8; i++)
#pragma unroll
                for (int j = 0; j < 8; j++)
                    acc[i][j] = fmaf(ra[i], rb[j], acc[i][j]);
        }
        __syncthreads();
    }

    // ---- epilogue: bias add + store ----
#pragma unroll
    for (int i = 0; i < 8; i++) {
        int gm = m0 + ty * 8 + i;
        if (gm >= M) continue;
#pragma unroll
        for (int j = 0; j < 8; j++) {
            int gn = n0 + tx * 8 + j;
            if (gn < N) C[(size_t)gm * N + gn] = acc[i][j] + bias[gn];
        }
    }
}

// ---------------------------------------------------------------------------
// fold + normalize + border-mask (gather form, no atomics)
// pix[b,c,iy,ix] = (interior ? sum(h over covering patches)/count : 0)
// ---------------------------------------------------------------------------
__global__ void fold_div_kernel(const float* __restrict__ h, float* __restrict__ pix)
{
    int idx = blockIdx.x * blockDim.x + threadIdx.x;
    if (idx >= NPIX) return;
    int ix = idx % WP;
    int t  = idx / WP;
    int iy = t % HP;  t /= HP;
    int c  = t % NCH;
    int b  = t / NCH;

    float val = 0.0f;
    if (iy >= 3 && iy < 63 && ix >= 3 && ix < 111) {
        int oy_lo = max(0, (iy - 4) / 3);   // ceil((iy-6)/3) clamped (iy>=3)
        int oy_hi = min(OH - 1, iy / 3);
        int ox_lo = max(0, (ix - 4) / 3);
        int ox_hi = min(OW - 1, ix / 3);
        int cnt = (oy_hi - oy_lo + 1) * (ox_hi - ox_lo + 1);
        float acc = 0.0f;
        for (int oy = oy_lo; oy <= oy_hi; oy++) {
            int kh = iy - 3 * oy;
            for (int ox = ox_lo; ox <= ox_hi; ox++) {
                int kw = ix - 3 * ox;
                int token = b * LVEC + oy * OW + ox;
                acc += h[(size_t)token * HID + c * 49 + kh * 7 + kw];
            }
        }
        val = acc / (float)cnt;
    }
    pix[idx] = val;
}

// ---------------------------------------------------------------------------
// unfold: y[token, cfull] = pix[b, c, kh+3*oy, kw+3*ox]
// ---------------------------------------------------------------------------
__global__ void unfold_kernel(const float* __restrict__ pix, float* __restrict__ y)
{
    long long idx = (long long)blockIdx.x * blockDim.x + threadIdx.x;
    if (idx >= (long long)M_TOK * HID) return;
    int cf    = (int)(idx % HID);
    int token = (int)(idx / HID);
    int b  = token / LVEC;
    int l  = token % LVEC;
    int oy = l / OW, ox = l % OW;
    int c  = cf / 49;
    int r  = cf % 49;
    int kh = r / 7, kw = r % 7;
    int iy = kh + 3 * oy;
    int ix = kw + 3 * ox;
    y[idx] = pix[(((size_t)b * NCH + c) * HP + iy) * WP + ix];
}

// ---------------------------------------------------------------------------
// launch
// ---------------------------------------------------------------------------
extern "C" void kernel_launch(void* const* d_in, const int* in_sizes, int n_in,
                              void* d_out, int out_size)
{
    const float* x  = (const float*)d_in[0];   // (2,5760,512)
    const float* W1 = (const float*)d_in[1];   // (1960,512)
    const float* b1 = (const float*)d_in[2];   // (1960,)
    const float* W2 = (const float*)d_in[3];   // (512,1960)
    const float* b2 = (const float*)d_in[4];   // (512,)
    float* out = (float*)d_out;                // (2,5760,512)

    float *h_ptr, *pix_ptr, *y_ptr;
    cudaGetSymbolAddress((void**)&h_ptr,   g_h);
    cudaGetSymbolAddress((void**)&pix_ptr, g_pix);
    cudaGetSymbolAddress((void**)&y_ptr,   g_y);

    // GEMM1: h = x @ W1^T + b1     (11520 x 1960 x 512)
    {
        dim3 grid((HID + BN - 1) / BN, M_TOK / BM);
        sgemm_tn_bias<false><<<grid, 256>>>(x, W1, b1, h_ptr, M_TOK, HID, DIM);
    }
    // fold + normalize + mask
    {
        int threads = 256;
        int blocks  = (NPIX + threads - 1) / threads;
        fold_div_kernel<<<blocks, threads>>>(h_ptr, pix_ptr);
    }
    // unfold
    {
        long long n = (long long)M_TOK * HID;
        int threads = 256;
        int blocks  = (int)((n + threads - 1) / threads);
        unfold_kernel<<<blocks, threads>>>(pix_ptr, y_ptr);
    }
    // GEMM2: out = gelu(y) @ W2^T + b2   (11520 x 512 x 1960)
    {
        dim3 grid((DIM + BN - 1) / BN, M_TOK / BM);
        sgemm_tn_bias<true><<<grid, 256>>>(y_ptr, W2, b2, out, M_TOK, DIM, HID);
    }
}

// round 4
// speedup vs baseline: 5.9503x; 5.9503x over previous
#include <cuda_runtime.h>
#include <cuda_fp16.h>
#include <math.h>
#include <stdint.h>

// ---------------------------------------------------------------------------
// Problem constants
// ---------------------------------------------------------------------------
#define M_TOK   11520
#define DIM     512
#define HID     1960
#define BPRIME  16
#define NCH     40
#define OH      20
#define OW      36
#define LVEC    720
#define HP      66
#define WP      114
#define NPIX    (BPRIME*NCH*HP*WP)

#define N1PAD   2048           // HID padded to 128 for GEMM1 N
#define K2PAD   1984           // HID padded to 64 for GEMM2 K

// Scratch (__device__ globals; allocation-free rule)
__device__ float  g_h  [(size_t)M_TOK * HID];
__device__ float  g_pix[(size_t)NPIX];
__device__ __half g_A1 [(size_t)M_TOK * DIM];
__device__ __half g_B1 [(size_t)N1PAD * DIM];
__device__ __half g_A2 [(size_t)M_TOK * K2PAD];
__device__ __half g_B2 [(size_t)DIM   * K2PAD];

__device__ __forceinline__ float gelu_exact(float v) {
    return 0.5f * v * (1.0f + erff(v * 0.70710678118654752f));
}

// ---------------------------------------------------------------------------
// operand prep kernels
// ---------------------------------------------------------------------------
__global__ void prep_x_kernel(const float* __restrict__ x, __half* __restrict__ A1)
{
    int idx = blockIdx.x * blockDim.x + threadIdx.x;
    if (idx >= M_TOK * DIM) return;
    A1[idx] = __float2half(x[idx]);
}

__global__ void prep_W1_kernel(const float* __restrict__ W1, __half* __restrict__ B1)
{
    int idx = blockIdx.x * blockDim.x + threadIdx.x;
    if (idx >= N1PAD * DIM) return;
    int n = idx / DIM, k = idx - n * DIM;
    float v = (n < HID) ? W1[(size_t)n * DIM + k] : 0.0f;
    B1[idx] = __float2half(v);
}

__global__ void prep_W2_kernel(const float* __restrict__ W2, __half* __restrict__ B2)
{
    int idx = blockIdx.x * blockDim.x + threadIdx.x;
    if (idx >= DIM * K2PAD) return;
    int n = idx / K2PAD, j = idx - n * K2PAD;
    float v = (j < HID) ? W2[(size_t)n * HID + j] : 0.0f;
    B2[idx] = __float2half(v);
}

// fused unfold + GELU -> fp16 A2
__global__ void prep_A2_kernel(const float* __restrict__ pix, __half* __restrict__ A2)
{
    long long idx = (long long)blockIdx.x * blockDim.x + threadIdx.x;
    if (idx >= (long long)M_TOK * K2PAD) return;
    int token = (int)(idx / K2PAD);
    int j     = (int)(idx - (long long)token * K2PAD);
    float g = 0.0f;
    if (j < HID) {
        int b  = token / LVEC;
        int l  = token - b * LVEC;
        int oy = l / OW, ox = l - oy * OW;
        int c  = j / 49;
        int r  = j - c * 49;
        int kh = r / 7, kw = r - kh * 7;
        int iy = kh + 3 * oy;
        int ix = kw + 3 * ox;
        float y = pix[(((size_t)b * NCH + c) * HP + iy) * WP + ix];
        g = gelu_exact(y);
    }
    A2[idx] = __float2half(g);
}

// ---------------------------------------------------------------------------
// fold + normalize + border-mask (gather, no atomics)
// ---------------------------------------------------------------------------
__global__ void fold_div_kernel(const float* __restrict__ h, float* __restrict__ pix)
{
    int idx = blockIdx.x * blockDim.x + threadIdx.x;
    if (idx >= NPIX) return;
    int ix = idx % WP;
    int t  = idx / WP;
    int iy = t % HP;  t /= HP;
    int c  = t % NCH;
    int b  = t / NCH;

    float val = 0.0f;
    if (iy >= 3 && iy < 63 && ix >= 3 && ix < 111) {
        int oy_lo = max(0, (iy - 4) / 3);
        int oy_hi = min(OH - 1, iy / 3);
        int ox_lo = max(0, (ix - 4) / 3);
        int ox_hi = min(OW - 1, ix / 3);
        int cnt = (oy_hi - oy_lo + 1) * (ox_hi - ox_lo + 1);
        float acc = 0.0f;
        for (int oy = oy_lo; oy <= oy_hi; oy++) {
            int kh = iy - 3 * oy;
            for (int ox = ox_lo; ox <= ox_hi; ox++) {
                int kw = ix - 3 * ox;
                int token = b * LVEC + oy * OW + ox;
                acc += h[(size_t)token * HID + c * 49 + kh * 7 + kw];
            }
        }
        val = acc / (float)cnt;
    }
    pix[idx] = val;
}

// ---------------------------------------------------------------------------
// fp16 tensor-core GEMM via mma.sync (portable PTX, runs on sm_103 target)
// C[m,n] = sum_k A[m,k]*B[n,k] + bias[n]
// A [M,K] fp16 K-major, B [Npad,K] fp16 K-major, C fp32 [*, ldc]
// BM=BN=128, BK=64 halves (128B rows, SW128 swizzle), 3-stage cp.async,
// 256 threads = 8 warps (4 m x 2 n), warp tile 32x64.
// ---------------------------------------------------------------------------
#define STAGES      3
#define STAGE_BYTES 32768       // A 16KB + B 16KB
#define GEMM_SMEM   (STAGES * STAGE_BYTES)

__device__ __forceinline__ uint32_t smem_u32(const void* p) {
    return (uint32_t)__cvta_generic_to_shared(p);
}

__device__ __forceinline__ void load_stage(uint32_t sbase, const char* Ab, const char* Bb,
                                           int kbytes, int s, int kt, int tid)
{
    uint32_t st = sbase + s * STAGE_BYTES;
    size_t koff = (size_t)kt * 128;
#pragma unroll
    for (int i = 0; i < 4; i++) {
        int id  = tid + i * 256;           // 0..1023
        int row = id >> 3;
        int c   = id & 7;
        uint32_t so = (uint32_t)(row * 128 + ((c ^ (row & 7)) << 4));
        const char* ga = Ab + (size_t)row * kbytes + koff + ((size_t)c << 4);
        const char* gb = Bb + (size_t)row * kbytes + koff + ((size_t)c << 4);
        asm volatile("cp.async.cg.shared.global [%0], [%1], 16;" :: "r"(st + so),         "l"(ga) : "memory");
        asm volatile("cp.async.cg.shared.global [%0], [%1], 16;" :: "r"(st + 16384 + so), "l"(gb) : "memory");
    }
    asm volatile("cp.async.commit_group;" ::: "memory");
}

__global__ __launch_bounds__(256, 2)
void gemm_fp16_mma(const __half* __restrict__ A, const __half* __restrict__ B,
                   const float* __restrict__ bias, float* __restrict__ C,
                   int KT, int kbytes, int Nstore, int ldc)
{
    extern __shared__ char smem[];
    uint32_t sbase = smem_u32(smem);
    const int tid  = threadIdx.x;
    const int wid  = tid >> 5;
    const int lane = tid & 31;
    const int wm   = wid >> 1;          // 0..3  -> m offset 32*wm
    const int wn   = wid & 1;           // 0..1  -> n offset 64*wn
    const int m0   = blockIdx.y * 128;
    const int n0   = blockIdx.x * 128;

    const char* Ab = (const char*)A + (size_t)m0 * kbytes;
    const char* Bb = (const char*)B + (size_t)n0 * kbytes;

    float acc[2][8][4];
#pragma unroll
    for (int i = 0; i < 2; i++)
#pragma unroll
        for (int j = 0; j < 8; j++)
#pragma unroll
            for (int q = 0; q < 4; q++) acc[i][j][q] = 0.0f;

    // prologue: fill stages 0..STAGES-2
#pragma unroll
    for (int p = 0; p < STAGES - 1; p++) load_stage(sbase, Ab, Bb, kbytes, p, p, tid);

    const int lrow = lane & 15;         // ldmatrix row within 16
    const int lch  = lane >> 4;         // ldmatrix 16B-chunk select (0/1)

    for (int kt = 0; kt < KT; kt++) {
        int s = kt % STAGES;
        asm volatile("cp.async.wait_group 1;" ::: "memory");
        __syncthreads();

        // issue next stage load (targets stage computed last iteration — safe after sync)
        int ktn = kt + STAGES - 1;
        if (ktn < KT) load_stage(sbase, Ab, Bb, kbytes, ktn % STAGES, ktn, tid);
        else          asm volatile("cp.async.commit_group;" ::: "memory");

        uint32_t sA = sbase + s * STAGE_BYTES;
        uint32_t sB = sA + 16384;

#pragma unroll
        for (int k16 = 0; k16 < 4; k16++) {
            uint32_t a[2][4];
#pragma unroll
            for (int i = 0; i < 2; i++) {
                int r = wm * 32 + i * 16 + lrow;
                uint32_t addr = sA + r * 128 + (((2 * k16 + lch) ^ (r & 7)) << 4);
                asm volatile("ldmatrix.sync.aligned.m8n8.x4.shared.b16 {%0,%1,%2,%3}, [%4];"
                             : "=r"(a[i][0]), "=r"(a[i][1]), "=r"(a[i][2]), "=r"(a[i][3])
                             : "r"(addr));
            }
            uint32_t b[4][4];
#pragma unroll
            for (int j = 0; j < 4; j++) {
                int r = wn * 64 + j * 16 + lrow;
                uint32_t addr = sB + r * 128 + (((2 * k16 + lch) ^ (r & 7)) << 4);
                asm volatile("ldmatrix.sync.aligned.m8n8.x4.shared.b16 {%0,%1,%2,%3}, [%4];"
                             : "=r"(b[j][0]), "=r"(b[j][1]), "=r"(b[j][2]), "=r"(b[j][3])
                             : "r"(addr));
            }
#pragma unroll
            for (int i = 0; i < 2; i++) {
#pragma unroll
                for (int jn = 0; jn < 8; jn++) {
                    int jj = jn >> 1;
                    uint32_t b0 = (jn & 1) ? b[jj][1] : b[jj][0];
                    uint32_t b1 = (jn & 1) ? b[jj][3] : b[jj][2];
                    asm volatile(
                        "mma.sync.aligned.m16n8k16.row.col.f32.f16.f16.f32 "
                        "{%0,%1,%2,%3}, {%4,%5,%6,%7}, {%8,%9}, {%0,%1,%2,%3};"
                        : "+f"(acc[i][jn][0]), "+f"(acc[i][jn][1]),
                          "+f"(acc[i][jn][2]), "+f"(acc[i][jn][3])
                        : "r"(a[i][0]), "r"(a[i][1]), "r"(a[i][2]), "r"(a[i][3]),
                          "r"(b0), "r"(b1));
                }
            }
        }
    }

    // epilogue: bias + store fp32 (float2)
    const int g  = lane >> 2;
    const int tg = lane & 3;
#pragma unroll
    for (int i = 0; i < 2; i++) {
        int r0 = m0 + wm * 32 + i * 16 + g;
#pragma unroll
        for (int jn = 0; jn < 8; jn++) {
            int col = n0 + wn * 64 + jn * 8 + tg * 2;
            if (col < Nstore) {
                float bx = bias[col], by = bias[col + 1];
                float2 v0 = make_float2(acc[i][jn][0] + bx, acc[i][jn][1] + by);
                float2 v1 = make_float2(acc[i][jn][2] + bx, acc[i][jn][3] + by);
                *reinterpret_cast<float2*>(C + (size_t)r0      * ldc + col) = v0;
                *reinterpret_cast<float2*>(C + (size_t)(r0 + 8) * ldc + col) = v1;
            }
        }
    }
}

// ---------------------------------------------------------------------------
// launch
// ---------------------------------------------------------------------------
extern "C" void kernel_launch(void* const* d_in, const int* in_sizes, int n_in,
                              void* d_out, int out_size)
{
    const float* x  = (const float*)d_in[0];
    const float* W1 = (const float*)d_in[1];
    const float* b1 = (const float*)d_in[2];
    const float* W2 = (const float*)d_in[3];
    const float* b2 = (const float*)d_in[4];
    float* out = (float*)d_out;

    float *h_ptr, *pix_ptr;
    __half *A1, *B1, *A2, *B2;
    cudaGetSymbolAddress((void**)&h_ptr,   g_h);
    cudaGetSymbolAddress((void**)&pix_ptr, g_pix);
    cudaGetSymbolAddress((void**)&A1, g_A1);
    cudaGetSymbolAddress((void**)&B1, g_B1);
    cudaGetSymbolAddress((void**)&A2, g_A2);
    cudaGetSymbolAddress((void**)&B2, g_B2);

    cudaFuncSetAttribute(gemm_fp16_mma, cudaFuncAttributeMaxDynamicSharedMemorySize, GEMM_SMEM);

    { int n = M_TOK * DIM;   prep_x_kernel <<<(n + 255) / 256, 256>>>(x,  A1); }
    { int n = N1PAD * DIM;   prep_W1_kernel<<<(n + 255) / 256, 256>>>(W1, B1); }
    { int n = DIM * K2PAD;   prep_W2_kernel<<<(n + 255) / 256, 256>>>(W2, B2); }

    // GEMM1: g_h = x @ W1^T + b1   (M=11520, N=1960(pad 2048), K=512)
    {
        dim3 grid(N1PAD / 128, M_TOK / 128);
        gemm_fp16_mma<<<grid, 256, GEMM_SMEM>>>(A1, B1, b1, h_ptr,
                                                DIM / 64, DIM * 2, HID, HID);
    }
    // fold + normalize + mask
    {
        int blocks = (NPIX + 255) / 256;
        fold_div_kernel<<<blocks, 256>>>(h_ptr, pix_ptr);
    }
    // unfold + GELU -> A2
    {
        long long n = (long long)M_TOK * K2PAD;
        prep_A2_kernel<<<(int)((n + 255) / 256), 256>>>(pix_ptr, A2);
    }
    // GEMM2: out = gelu(y) @ W2^T + b2   (M=11520, N=512, K=1960(pad 1984))
    {
        dim3 grid(DIM / 128, M_TOK / 128);
        gemm_fp16_mma<<<grid, 256, GEMM_SMEM>>>(A2, B2, b2, out,
                                                K2PAD / 64, K2PAD * 2, DIM, DIM);
    }
}